// round 3
// baseline (speedup 1.0000x reference)
#include <cuda_runtime.h>
#include <math.h>

// Problem shape (fixed by the dataset instance)
#define BATCH 16
#define HEADS 8
#define HDIM  128
#define BSIZE 16               // tokens per cache block
#define BPS   128              // blocks per sequence
#define TMAX  (BSIZE * BPS)    // 2048 tokens
#define NSPLIT 8
#define TSPLIT (TMAX / NSPLIT)     // 256 tokens per split
#define BLKSPLIT (TSPLIT / BSIZE)  // 16 cache blocks per split
#define THREADS 128
#define NWARPS  (THREADS / 32)     // 4
#define TPW     (TSPLIT / NWARPS)  // 64 tokens per warp
#define GROUP 8

// split-KV partials + completion counters (allocation-free scratch, zero-init)
__device__ float g_part_o[BATCH * HEADS * NSPLIT * HDIM];
__device__ float g_part_m[BATCH * HEADS * NSPLIT];
__device__ float g_part_l[BATCH * HEADS * NSPLIT];
__device__ unsigned int g_cnt[BATCH * HEADS];

__device__ __forceinline__ float warp_sum(float v) {
#pragma unroll
    for (int o = 16; o > 0; o >>= 1) v += __shfl_xor_sync(0xffffffffu, v, o);
    return v;
}

__global__ __launch_bounds__(THREADS, 2)
void paged_attn_fused_kernel(const float* __restrict__ q,
                             const float* __restrict__ knew,
                             const float* __restrict__ vnew,
                             const float* __restrict__ kcache,
                             const float* __restrict__ vcache,
                             const int*   __restrict__ block_tables,
                             const int*   __restrict__ context_lens,
                             float*       __restrict__ out)
{
    const float SCALE = 0.08838834764831845f;

    const int bh    = blockIdx.x >> 3;           // / NSPLIT
    const int split = blockIdx.x & (NSPLIT - 1);
    const int b     = bh / HEADS;
    const int h     = bh % HEADS;
    const int tid   = threadIdx.x;
    const int lane  = tid & 31;
    const int w     = tid >> 5;
    const int tbase = split * TSPLIT;

    __shared__ int   s_bt[BLKSPLIT];
    __shared__ float s_m[NWARPS];
    __shared__ float s_l[NWARPS];
    __shared__ float s_acc[NWARPS][HDIM];
    __shared__ unsigned int s_last;

    if (tid < BLKSPLIT)
        s_bt[tid] = block_tables[b * BPS + split * BLKSPLIT + tid];

    const int ctx  = context_lens[b];
    const int last = ctx - 1;

    float4 q4 = reinterpret_cast<const float4*>(q + (size_t)(b * HEADS + h) * HDIM)[lane];
    q4.x *= SCALE; q4.y *= SCALE; q4.z *= SCALE; q4.w *= SCALE;

    const float* kfresh = knew + (size_t)(b * HEADS + h) * HDIM;
    const float* vfresh = vnew + (size_t)(b * HEADS + h) * HDIM;

    __syncthreads();

    // ------------- single pass: online softmax over this warp's tokens -----
    float  m = -INFINITY;
    float  l = 0.f;
    float4 acc = make_float4(0.f, 0.f, 0.f, 0.f);

    const int lbeg = w * TPW;
#pragma unroll 1
    for (int l0 = lbeg; l0 < lbeg + TPW; l0 += GROUP) {
        size_t rows[GROUP];
        int    isLast[GROUP];
#pragma unroll
        for (int i = 0; i < GROUP; i++) {
            const int lt = l0 + i;
            const int t  = tbase + lt;
            const int blk = s_bt[lt >> 4];
            rows[i]   = ((size_t)blk * BSIZE + (t & (BSIZE - 1))) * HEADS + h;
            isLast[i] = (t == last);
        }
        float4 kv[GROUP];
        float4 vv[GROUP];
#pragma unroll
        for (int i = 0; i < GROUP; i++) {
            const float* kr = isLast[i] ? kfresh : (kcache + rows[i] * HDIM);
            kv[i] = reinterpret_cast<const float4*>(kr)[lane];
        }
#pragma unroll
        for (int i = 0; i < GROUP; i++) {
            const float* vr = isLast[i] ? vfresh : (vcache + rows[i] * HDIM);
            vv[i] = reinterpret_cast<const float4*>(vr)[lane];
        }

        float s[GROUP];
#pragma unroll
        for (int i = 0; i < GROUP; i++) {
            float d = kv[i].x * q4.x + kv[i].y * q4.y + kv[i].z * q4.z + kv[i].w * q4.w;
            d = warp_sum(d);                         // result in all lanes
            s[i] = (tbase + l0 + i < ctx) ? d : -INFINITY;
        }

        float gm = s[0];
#pragma unroll
        for (int i = 1; i < GROUP; i++) gm = fmaxf(gm, s[i]);
        const float nm = fmaxf(m, gm);
        if (nm != -INFINITY) {
            const float scale = __expf(m - nm);      // m=-inf first iter -> 0
            l *= scale;
            acc.x *= scale; acc.y *= scale; acc.z *= scale; acc.w *= scale;
#pragma unroll
            for (int i = 0; i < GROUP; i++) {
                const float p = __expf(s[i] - nm);   // masked -> exp(-inf)=0
                l += p;
                acc.x += p * vv[i].x;
                acc.y += p * vv[i].y;
                acc.z += p * vv[i].z;
                acc.w += p * vv[i].w;
            }
            m = nm;
        }
    }

    // ------------- cross-warp merge -> split partial ------------------------
    if (lane == 0) { s_m[w] = m; s_l[w] = l; }
    reinterpret_cast<float4*>(s_acc[w])[lane] = acc;
    __syncthreads();

    float M = -INFINITY;
#pragma unroll
    for (int ww = 0; ww < NWARPS; ww++) M = fmaxf(M, s_m[ww]);

    const int ps = bh * NSPLIT + split;
    if (tid < HDIM) {
        float r = 0.f;
#pragma unroll
        for (int ww = 0; ww < NWARPS; ww++) {
            const float coef = (s_m[ww] == -INFINITY) ? 0.f : __expf(s_m[ww] - M);
            r += coef * s_acc[ww][tid];
        }
        g_part_o[(size_t)ps * HDIM + tid] = r;
    }
    if (tid == 0) {
        float L = 0.f;
#pragma unroll
        for (int ww = 0; ww < NWARPS; ww++) {
            const float coef = (s_m[ww] == -INFINITY) ? 0.f : __expf(s_m[ww] - M);
            L += coef * s_l[ww];
        }
        g_part_m[ps] = M;
        g_part_l[ps] = L;
    }

    // ------------- last CTA per (b,h) combines ------------------------------
    __threadfence();
    __syncthreads();
    if (tid == 0)
        s_last = atomicAdd(&g_cnt[bh], 1u);
    __syncthreads();
    if (s_last != NSPLIT - 1) return;

    if (tid < HDIM) {
        float Mg = -INFINITY;
#pragma unroll
        for (int i = 0; i < NSPLIT; i++)
            Mg = fmaxf(Mg, g_part_m[bh * NSPLIT + i]);
        float Lg = 0.f, r = 0.f;
#pragma unroll
        for (int i = 0; i < NSPLIT; i++) {
            const float mi = g_part_m[bh * NSPLIT + i];
            const float coef = (mi == -INFINITY) ? 0.f : __expf(mi - Mg);
            Lg += coef * g_part_l[bh * NSPLIT + i];
            r  += coef * g_part_o[((size_t)bh * NSPLIT + i) * HDIM + tid];
        }
        out[(size_t)bh * HDIM + tid] = r / Lg;
    }
    if (tid == 0) g_cnt[bh] = 0;   // reset for next graph replay
}

extern "C" void kernel_launch(void* const* d_in, const int* in_sizes, int n_in,
                              void* d_out, int out_size)
{
    const float* q            = (const float*)d_in[0];
    const float* k            = (const float*)d_in[1];
    const float* v            = (const float*)d_in[2];
    const float* k_cache      = (const float*)d_in[3];
    const float* v_cache      = (const float*)d_in[4];
    // d_in[5] = slot_mapping (unused: substitution at t == ctx-1 is equivalent)
    const int*   block_tables = (const int*)d_in[6];
    const int*   context_lens = (const int*)d_in[7];
    float*       out          = (float*)d_out;

    paged_attn_fused_kernel<<<BATCH * HEADS * NSPLIT, THREADS>>>(
        q, k, v, k_cache, v_cache, block_tables, context_lens, out);
}

// round 4
// speedup vs baseline: 1.1855x; 1.1855x over previous
#include <cuda_runtime.h>
#include <math.h>

// Problem shape (fixed by the dataset instance)
#define BATCH 16
#define HEADS 8
#define HDIM  128
#define BSIZE 16               // tokens per cache block
#define BPS   128              // blocks per sequence
#define TMAX  (BSIZE * BPS)    // 2048 tokens
#define NSPLIT 4
#define TSPLIT (TMAX / NSPLIT)     // 512 tokens per split
#define BLKSPLIT (TSPLIT / BSIZE)  // 32 cache blocks per split
#define THREADS 256
#define NWARPS  (THREADS / 32)     // 8
#define TPW     (TSPLIT / NWARPS)  // 64 tokens per warp

// split-KV partials + completion counters (allocation-free scratch, zero-init)
__device__ float g_part_o[BATCH * HEADS * NSPLIT * HDIM];
__device__ float g_part_m[BATCH * HEADS * NSPLIT];
__device__ float g_part_l[BATCH * HEADS * NSPLIT];
__device__ unsigned int g_cnt[BATCH * HEADS];

__device__ __forceinline__ float warp_sum(float v) {
#pragma unroll
    for (int o = 16; o > 0; o >>= 1) v += __shfl_xor_sync(0xffffffffu, v, o);
    return v;
}
__device__ __forceinline__ float warp_max(float v) {
#pragma unroll
    for (int o = 16; o > 0; o >>= 1) v = fmaxf(v, __shfl_xor_sync(0xffffffffu, v, o));
    return v;
}

__global__ __launch_bounds__(THREADS)
void paged_attn_split_kernel(const float* __restrict__ q,
                             const float* __restrict__ knew,
                             const float* __restrict__ vnew,
                             const float* __restrict__ kcache,
                             const float* __restrict__ vcache,
                             const int*   __restrict__ block_tables,
                             const int*   __restrict__ context_lens,
                             float*       __restrict__ out)
{
    const float SCALE = 0.08838834764831845f;

    const int bh    = blockIdx.x >> 2;          // / NSPLIT
    const int split = blockIdx.x & (NSPLIT - 1);
    const int b     = bh / HEADS;
    const int h     = bh % HEADS;
    const int tid   = threadIdx.x;
    const int lane  = tid & 31;
    const int w     = tid >> 5;
    const int tbase = split * TSPLIT;

    __shared__ float s_scores[TSPLIT];
    __shared__ int   s_bt[BLKSPLIT];
    __shared__ float s_red[NWARPS];
    __shared__ float s_acc[NWARPS][HDIM];
    __shared__ float s_bcast[2];
    __shared__ unsigned int s_last;

    if (tid < BLKSPLIT)
        s_bt[tid] = block_tables[b * BPS + split * BLKSPLIT + tid];

    const int ctx  = context_lens[b];
    const int last = ctx - 1;

    float4 q4 = reinterpret_cast<const float4*>(q + (size_t)(b * HEADS + h) * HDIM)[lane];
    q4.x *= SCALE; q4.y *= SCALE; q4.z *= SCALE; q4.w *= SCALE;

    const float* kfresh = knew + (size_t)(b * HEADS + h) * HDIM;
    const float* vfresh = vnew + (size_t)(b * HEADS + h) * HDIM;

    __syncthreads();

    // ------------- Phase 1: scores (8-deep load batches per warp) ----------
    const int lbeg = w * TPW;
#pragma unroll 1
    for (int l0 = lbeg; l0 < lbeg + TPW; l0 += 8) {
        float4 kv[8];
#pragma unroll
        for (int i = 0; i < 8; i++) {
            const int lt = l0 + i;                 // local token in split
            const int t  = tbase + lt;             // global token
            const int blk = s_bt[lt >> 4];
            const size_t row = ((size_t)blk * BSIZE + (t & (BSIZE - 1))) * HEADS + h;
            const float* kr = (t == last) ? kfresh : (kcache + row * HDIM);
            kv[i] = reinterpret_cast<const float4*>(kr)[lane];
        }
#pragma unroll
        for (int i = 0; i < 8; i++) {
            float s = kv[i].x * q4.x + kv[i].y * q4.y + kv[i].z * q4.z + kv[i].w * q4.w;
            s = warp_sum(s);
            if (lane == i) {
                const int lt = l0 + i;
                s_scores[lt] = (tbase + lt < ctx) ? s : -INFINITY;
            }
        }
    }
    __syncthreads();

    // ------------- Phase 2: local softmax (partial m, l) -------------------
    float m = -INFINITY;
    for (int i = tid; i < TSPLIT; i += THREADS) m = fmaxf(m, s_scores[i]);
    m = warp_max(m);
    if (lane == 0) s_red[w] = m;
    __syncthreads();
    if (w == 0) {
        float mm = (lane < NWARPS) ? s_red[lane] : -INFINITY;
        mm = warp_max(mm);
        if (lane == 0) s_bcast[0] = mm;
    }
    __syncthreads();
    m = s_bcast[0];
    const float msafe = (m == -INFINITY) ? 0.0f : m;  // avoid inf-inf = NaN

    float psum = 0.f;
    for (int i = tid; i < TSPLIT; i += THREADS) {
        float e = __expf(s_scores[i] - msafe);
        s_scores[i] = e;
        psum += e;
    }
    psum = warp_sum(psum);
    if (lane == 0) s_red[w] = psum;
    __syncthreads();
    if (w == 0) {
        float ss = (lane < NWARPS) ? s_red[lane] : 0.f;
        ss = warp_sum(ss);
        if (lane == 0) s_bcast[1] = ss;
    }

    // ------------- Phase 3: unnormalized o = sum p_t v_t -------------------
    float4 acc = make_float4(0.f, 0.f, 0.f, 0.f);
#pragma unroll 1
    for (int l0 = lbeg; l0 < lbeg + TPW; l0 += 8) {
        float4 vv[8];
        float  p[8];
#pragma unroll
        for (int i = 0; i < 8; i++) {
            const int lt = l0 + i;
            const int t  = tbase + lt;
            const int blk = s_bt[lt >> 4];
            const size_t row = ((size_t)blk * BSIZE + (t & (BSIZE - 1))) * HEADS + h;
            const float* vr = (t == last) ? vfresh : (vcache + row * HDIM);
            vv[i] = reinterpret_cast<const float4*>(vr)[lane];
            p[i]  = s_scores[lt];
        }
#pragma unroll
        for (int i = 0; i < 8; i++) {
            acc.x += p[i] * vv[i].x;
            acc.y += p[i] * vv[i].y;
            acc.z += p[i] * vv[i].z;
            acc.w += p[i] * vv[i].w;
        }
    }
    reinterpret_cast<float4*>(s_acc[w])[lane] = acc;
    __syncthreads();

    // ------------- write this split's partial -------------------------------
    const int ps = bh * NSPLIT + split;
    if (tid < HDIM) {
        float r = 0.f;
#pragma unroll
        for (int ww = 0; ww < NWARPS; ww++) r += s_acc[ww][tid];
        g_part_o[(size_t)ps * HDIM + tid] = r;
    }
    if (tid == 0) {
        g_part_m[ps] = m;
        g_part_l[ps] = s_bcast[1];
    }

    // ------------- last CTA per (b,h) combines (fused, no 2nd launch) ------
    __threadfence();
    __syncthreads();
    if (tid == 0)
        s_last = atomicAdd(&g_cnt[bh], 1u);
    __syncthreads();
    if (s_last != NSPLIT - 1) return;

    if (tid < HDIM) {
        float Mg = -INFINITY;
#pragma unroll
        for (int i = 0; i < NSPLIT; i++)
            Mg = fmaxf(Mg, g_part_m[bh * NSPLIT + i]);
        float Lg = 0.f, r = 0.f;
#pragma unroll
        for (int i = 0; i < NSPLIT; i++) {
            const float mi = g_part_m[bh * NSPLIT + i];
            const float coef = (mi == -INFINITY) ? 0.f : __expf(mi - Mg);
            Lg += coef * g_part_l[bh * NSPLIT + i];
            r  += coef * g_part_o[((size_t)bh * NSPLIT + i) * HDIM + tid];
        }
        out[(size_t)bh * HDIM + tid] = r / Lg;
    }
    if (tid == 0) g_cnt[bh] = 0;   // reset for next graph replay
}

extern "C" void kernel_launch(void* const* d_in, const int* in_sizes, int n_in,
                              void* d_out, int out_size)
{
    const float* q            = (const float*)d_in[0];
    const float* k            = (const float*)d_in[1];
    const float* v            = (const float*)d_in[2];
    const float* k_cache      = (const float*)d_in[3];
    const float* v_cache      = (const float*)d_in[4];
    // d_in[5] = slot_mapping (unused: substitution at t == ctx-1 is equivalent)
    const int*   block_tables = (const int*)d_in[6];
    const int*   context_lens = (const int*)d_in[7];
    float*       out          = (float*)d_out;

    paged_attn_split_kernel<<<BATCH * HEADS * NSPLIT, THREADS>>>(
        q, k, v, k_cache, v_cache, block_tables, context_lens, out);
}